// round 15
// baseline (speedup 1.0000x reference)
#include <cuda_runtime.h>
#include <cuda_bf16.h>
#include <cuda_fp16.h>
#include <cstdint>

// Problem constants
constexpr int NN   = 50000;
constexpr int NE   = 640000;
constexpr int RR   = 3;
constexpr int HID  = 128;
constexpr int GG   = 512;
constexpr int K1   = 129;   // logical layer-1 K (row 128 handled as rank-1 update)
constexpr int KC   = 128;   // GEMM K for both layers
constexpr int SEG  = RR * NN;
constexpr int SCAN_T = 256;
constexpr int SCAN_V = 4;
constexpr int SCAN_E = SCAN_T * SCAN_V;
constexpr int NBLK = (SEG + SCAN_E - 1) / SCAN_E;

// GEMM tiling: BM=128, BN=128, BK=32, whole-K prefetch (4 slots), 256 threads
constexpr int KT_C   = KC / 32;                   // 4 chunks
constexpr int RSTR   = 40;                        // row stride in halfs (80B, conflict-free)
constexpr int PLANE  = 128 * RSTR;
constexpr int STG_EL = 2 * PLANE;                 // A | B per slot
constexpr int SMEM_BYTES = KT_C * STG_EL * 2;     // 81920 B

// ---------------- PDL helpers ----------------------------------------------------------
__device__ __forceinline__ void pdl_wait() {
    asm volatile("griddepcontrol.wait;" ::: "memory");
}

// ---------------- scratch -------------------------------------------------------------
__device__ __half g_A1[(size_t)NN * KC];
__device__ __half g_A2[(size_t)NN * KC];
__device__ __half g_B1[512 * KC];
__device__ __half g_B2[512 * KC];
__device__ float  g_wlast[512];                  // row 128 of [W1_0|W1_1|W1_2|root1]
__device__ __half g_Y1h[(size_t)4 * NN * HID];   // y0|y1|y2|h (fp16)
__device__ __half g_Y2h[(size_t)4 * NN * HID];
__device__ int   g_cnt[SEG];
__device__ float g_inv[SEG];
__device__ int   g_off[SEG];
__device__ int   g_cur[SEG];
__device__ int   g_bsum[NBLK];
__device__ int   g_csr[NE];
__device__ float g_pool[GG * HID];
__device__ int   g_gcnt[GG];

// ---------------- init / counting ------------------------------------------------------
__global__ void zero_misc_kernel() {
    int i = blockIdx.x * blockDim.x + threadIdx.x;
    if (i < SEG) g_cnt[i] = 0;
    if (i < GG * HID) g_pool[i] = 0.f;
    if (i < GG) g_gcnt[i] = 0;
}

__global__ void count_edges_kernel(const int* __restrict__ ei, const int* __restrict__ et) {
    int e = blockIdx.x * blockDim.x + threadIdx.x;
    if (e >= NE) return;
    atomicAdd(&g_cnt[et[e] * NN + ei[NE + e]], 1);
}

// ---------------- 3-kernel exclusive scan ----------------------------------------------
__global__ void scan1_kernel() {
    __shared__ int sh[SCAN_T];
    const int tid  = threadIdx.x;
    const int base = blockIdx.x * SCAN_E + tid * SCAN_V;
    int v[SCAN_V], s = 0;
    #pragma unroll
    for (int k = 0; k < SCAN_V; k++) {
        v[k] = (base + k < SEG) ? g_cnt[base + k] : 0;
        s += v[k];
    }
    sh[tid] = s;
    __syncthreads();
    for (int off = 1; off < SCAN_T; off <<= 1) {
        int t = (tid >= off) ? sh[tid - off] : 0;
        __syncthreads();
        sh[tid] += t;
        __syncthreads();
    }
    int run = sh[tid] - s;
    #pragma unroll
    for (int k = 0; k < SCAN_V; k++) {
        if (base + k < SEG) g_off[base + k] = run;
        run += v[k];
    }
    if (tid == SCAN_T - 1) g_bsum[blockIdx.x] = sh[tid];
}

__global__ void scan2_kernel() {
    __shared__ int sh[SCAN_T];
    const int tid = threadIdx.x;
    int v = (tid < NBLK) ? g_bsum[tid] : 0;
    sh[tid] = v;
    __syncthreads();
    for (int off = 1; off < SCAN_T; off <<= 1) {
        int t = (tid >= off) ? sh[tid - off] : 0;
        __syncthreads();
        sh[tid] += t;
        __syncthreads();
    }
    if (tid < NBLK) g_bsum[tid] = sh[tid] - v;
}

__global__ void scan3_kernel() {
    int i = blockIdx.x * blockDim.x + threadIdx.x;
    if (i >= SEG) return;
    int o = g_off[i] + g_bsum[i / SCAN_E];
    g_off[i] = o;
    g_cur[i] = o;
    int c = g_cnt[i];
    g_inv[i] = 1.f / (float)(c > 0 ? c : 1);
}

__global__ void fill_csr_kernel(const int* __restrict__ ei, const int* __restrict__ et) {
    int e = blockIdx.x * blockDim.x + threadIdx.x;
    if (e >= NE) return;
    int seg = et[e] * NN + ei[NE + e];
    int pos = atomicAdd(&g_cur[seg], 1);
    g_csr[pos] = ei[e];
}

// ---------------- fused prep: X1 build + B1/B2 conv + wlast ---------------------------
struct __align__(8) hf4 { __half v[4]; };

__device__ __forceinline__ void store4h(float4 v, __half* p) {
    hf4 h;
    h.v[0] = __float2half_rn(v.x);
    h.v[1] = __float2half_rn(v.y);
    h.v[2] = __float2half_rn(v.z);
    h.v[3] = __float2half_rn(v.w);
    *reinterpret_cast<hf4*>(p) = h;
}

constexpr int QW1     = KC / 4;                  // 32 quads per node
constexpr int PREP_X  = NN * QW1;
constexpr int PREP_B1 = 512 * KC;
constexpr int PREP_B2 = 512 * KC;
constexpr int PREP_WL = 512;
constexpr int PREP_TOT = PREP_X + PREP_B1 + PREP_B2 + PREP_WL;

__global__ void prep_kernel(const int* __restrict__ sid,
                            const int* __restrict__ cid,
                            const float* __restrict__ se,
                            const float* __restrict__ ce,
                            const float* __restrict__ W1, const float* __restrict__ root1,
                            const float* __restrict__ W2, const float* __restrict__ root2) {
    int idx = blockIdx.x * blockDim.x + threadIdx.x;
    if (idx < PREP_X) {
        int n = idx / QW1;
        int j = (idx - n * QW1) * 4;
        float4 v;
        if (j < 64) v = *reinterpret_cast<const float4*>(se + sid[n] * 64 + j);
        else        v = *reinterpret_cast<const float4*>(ce + cid[n] * 64 + (j - 64));
        store4h(v, &g_A1[(size_t)n * KC + j]);
    } else if (idx < PREP_X + PREP_B1) {
        int t  = idx - PREP_X;
        int nc = t / KC;
        int k  = t - nc * KC;
        int s  = nc >> 7;
        int n  = nc & 127;
        float v = (s < 3) ? W1[((size_t)s * K1 + k) * 128 + n]
                          : root1[(size_t)k * 128 + n];
        g_B1[t] = __float2half_rn(v);
    } else if (idx < PREP_X + PREP_B1 + PREP_B2) {
        int t  = idx - PREP_X - PREP_B1;
        int nc = t / KC;
        int k  = t - nc * KC;
        int s  = nc >> 7;
        int n  = nc & 127;
        float v = (s < 3) ? W2[((size_t)s * KC + k) * 128 + n]
                          : root2[(size_t)k * 128 + n];
        g_B2[t] = __float2half_rn(v);
    } else if (idx < PREP_TOT) {
        int t = idx - PREP_X - PREP_B1 - PREP_B2;   // 0..511
        int s = t >> 7;
        int n = t & 127;
        g_wlast[t] = (s < 3) ? W1[((size_t)s * K1 + 128) * 128 + n]
                             : root1[(size_t)128 * 128 + n];
    }
}

// ---------------- tensor-core GEMM v9: whole-K prefetch, barrier-free mainloop --------
__device__ __forceinline__ void cp16(uint32_t dst, const void* src) {
    asm volatile("cp.async.cg.shared.global [%0], [%1], 16;" :: "r"(dst), "l"(src));
}

__device__ __forceinline__ void mma_f16(float* c, const uint32_t* a, uint32_t b0, uint32_t b1) {
    asm volatile(
        "mma.sync.aligned.m16n8k16.row.col.f32.f16.f16.f32 "
        "{%0,%1,%2,%3}, {%4,%5,%6,%7}, {%8,%9}, {%0,%1,%2,%3};"
        : "+f"(c[0]), "+f"(c[1]), "+f"(c[2]), "+f"(c[3])
        : "r"(a[0]), "r"(a[1]), "r"(a[2]), "r"(a[3]), "r"(b0), "r"(b1));
}

__device__ __forceinline__ void ldmx4(uint32_t* r, uint32_t addr) {
    asm volatile("ldmatrix.sync.aligned.m8n8.x4.shared.b16 {%0,%1,%2,%3}, [%4];"
                 : "=r"(r[0]), "=r"(r[1]), "=r"(r[2]), "=r"(r[3]) : "r"(addr));
}

template <bool RANK1>
__global__ void __launch_bounds__(256, 2) gemm_tc_kernel(
    const __half* __restrict__ A,
    const __half* __restrict__ B,
    const float* __restrict__ bias,
    const float* __restrict__ pos,      // [N] (RANK1 only)
    const float* __restrict__ wlast,    // [512] (RANK1 only)
    __half* __restrict__ Yh)            // [4, N, 128] fp16
{
    extern __shared__ __align__(16) __half smem[];

    pdl_wait();   // predecessor (prep / aggregate) must be complete before reading A/B

    const int tid  = threadIdx.x;
    const int wid  = tid >> 5;
    const int lane = tid & 31;
    const int wm   = wid & 3;
    const int wn   = wid >> 2;
    const int m0   = blockIdx.x * 128;
    const int sec  = blockIdx.y;
    const int nrow0 = sec * 128;

    const uint32_t s_u32 = (uint32_t)__cvta_generic_to_shared(smem);

    float c[2][4][2][4] = {};

    // Prefetch ALL of K (4 chunks) in the prologue; one commit.
    #pragma unroll
    for (int ks = 0; ks < KT_C; ks++) {
        const int k0 = ks * 32;
        #pragma unroll
        for (int rep = 0; rep < 4; rep++) {
            int s = tid + rep * 256;
            int plane = s >> 9;
            int rr    = (s & 511) >> 2;
            int h     = s & 3;
            const __half* src;
            bool ok = true;
            if (plane == 0) {
                ok = (m0 + rr < NN);
                src = A + (size_t)(m0 + rr) * KC + k0 + h * 8;
            } else {
                src = B + (size_t)(nrow0 + rr) * KC + k0 + h * 8;
            }
            if (ok) {
                uint32_t dst = s_u32 +
                    ((ks * STG_EL + plane * PLANE + rr * RSTR + h * 8) << 1);
                cp16(dst, src);
            }
        }
    }
    asm volatile("cp.async.commit_group;" ::: "memory");
    asm volatile("cp.async.wait_group 0;" ::: "memory");
    __syncthreads();

    const int bgrp = lane >> 3;
    const int brow = lane & 7;
    const int bn_off = (bgrp & 2) ? 8 : 0;
    const int bk_off = (bgrp & 1) * 8;
    const int a_cof  = (lane >> 4) * 8;

    // Barrier-free mainloop: pure ldsm + MMA stream.
    #pragma unroll
    for (int ks = 0; ks < KT_C; ks++) {
        const uint32_t st_base = s_u32 + ((ks * STG_EL) << 1);
        #pragma unroll
        for (int kp = 0; kp < 2; kp++) {
            uint32_t ah[2][4];
            #pragma unroll
            for (int mt = 0; mt < 2; mt++) {
                int row = wm * 32 + mt * 16 + (lane & 15);
                ldmx4(ah[mt], st_base + ((row * RSTR + kp * 16 + a_cof) << 1));
            }
            #pragma unroll
            for (int ntp = 0; ntp < 4; ntp++) {
                const int n = wn * 64 + ntp * 16 + bn_off + brow;
                uint32_t bh[4];
                ldmx4(bh, st_base + ((PLANE + n * RSTR + kp * 16 + bk_off) << 1));
                #pragma unroll
                for (int mt = 0; mt < 2; mt++) {
                    mma_f16(c[mt][ntp][0], ah[mt], bh[0], bh[1]);
                    mma_f16(c[mt][ntp][1], ah[mt], bh[2], bh[3]);
                }
            }
        }
    }

    // epilogue: all sections fp16; +bias on sec 3; +pos*wlast rank-1 if RANK1
    __half* Ysec = Yh + (size_t)sec * NN * HID;
    #pragma unroll
    for (int mt = 0; mt < 2; mt++) {
        int row = m0 + wm * 32 + mt * 16 + (lane >> 2);
        float p0 = 0.f, p1 = 0.f;
        if (RANK1) {
            if (row < NN)     p0 = pos[row];
            if (row + 8 < NN) p1 = pos[row + 8];
        }
        #pragma unroll
        for (int ntp = 0; ntp < 4; ntp++) {
            #pragma unroll
            for (int ng = 0; ng < 2; ng++) {
                int col = wn * 64 + ntp * 16 + ng * 8 + (lane & 3) * 2;
                float* cc = c[mt][ntp][ng];
                float ax = 0.f, ay = 0.f;
                if (sec == 3) { ax = bias[col]; ay = bias[col + 1]; }
                if (RANK1) {
                    float wl0 = wlast[nrow0 + col];
                    float wl1 = wlast[nrow0 + col + 1];
                    cc[0] += p0 * wl0; cc[1] += p0 * wl1;
                    cc[2] += p1 * wl0; cc[3] += p1 * wl1;
                }
                if (row < NN)
                    *reinterpret_cast<__half2*>(Ysec + (size_t)row * HID + col) =
                        __floats2half2_rn(cc[0] + ax, cc[1] + ay);
                if (row + 8 < NN)
                    *reinterpret_cast<__half2*>(Ysec + (size_t)(row + 8) * HID + col) =
                        __floats2half2_rn(cc[2] + ax, cc[3] + ay);
            }
        }
    }
}

// ---------------- CSR gather aggregation (fp16, 4 sections) ----------------------------
template <int LAYER>
__global__ void aggregate_kernel(const int* __restrict__ batch,
                                 const __half* __restrict__ Yh) {
    pdl_wait();   // gemm must be complete before gathering Yh

    const int w = (blockIdx.x * blockDim.x + threadIdx.x) >> 5;
    if (w >= NN) return;
    const int lane = threadIdx.x & 31;
    const int lo8 = lane * 4;

    float4 acc;
    {
        uint2 raw = *reinterpret_cast<const uint2*>(
            Yh + (size_t)3 * NN * HID + (size_t)w * HID + lo8);
        float2 a = __half22float2(*reinterpret_cast<const __half2*>(&raw.x));
        float2 b = __half22float2(*reinterpret_cast<const __half2*>(&raw.y));
        acc = make_float4(a.x, a.y, b.x, b.y);
    }

    #pragma unroll
    for (int r = 0; r < RR; r++) {
        const int seg = r * NN + w;
        const int s0  = g_off[seg];
        const int c   = g_cnt[seg];
        const float sc = g_inv[seg];
        const __half* Yr = Yh + (size_t)r * NN * HID;
        float4 t = make_float4(0.f, 0.f, 0.f, 0.f);
        int nxt = (c > 0) ? g_csr[s0] : 0;
        for (int i = 0; i < c; i++) {
            int cur = nxt;
            if (i + 1 < c) nxt = g_csr[s0 + i + 1];
            uint2 raw = *reinterpret_cast<const uint2*>(
                Yr + (size_t)cur * HID + lo8);
            float2 a = __half22float2(*reinterpret_cast<const __half2*>(&raw.x));
            float2 b = __half22float2(*reinterpret_cast<const __half2*>(&raw.y));
            t.x += a.x; t.y += a.y; t.z += b.x; t.w += b.y;
        }
        acc.x += t.x * sc; acc.y += t.y * sc; acc.z += t.z * sc; acc.w += t.w * sc;
    }

    acc.x = fmaxf(acc.x, 0.f); acc.y = fmaxf(acc.y, 0.f);
    acc.z = fmaxf(acc.z, 0.f); acc.w = fmaxf(acc.w, 0.f);

    if (LAYER == 1) {
        store4h(acc, &g_A2[(size_t)w * KC + lo8]);
    } else {
        const int g = batch[w];
        float* o = g_pool + (size_t)g * HID + lo8;
        asm volatile("red.global.add.v4.f32 [%0], {%1, %2, %3, %4};"
                     :: "l"(o), "f"(acc.x), "f"(acc.y), "f"(acc.z), "f"(acc.w) : "memory");
        if (lane == 0) atomicAdd(&g_gcnt[g], 1);
    }
}

__global__ void final_kernel(const float* __restrict__ lw, const float* __restrict__ lb,
                             float* __restrict__ out) {
    pdl_wait();
    int g = blockIdx.x * blockDim.x + threadIdx.x;
    if (g >= GG) return;
    const int c = g_gcnt[g];
    const float inv = 1.f / (float)(c > 0 ? c : 1);
    float a0 = 0.f, a1 = 0.f, a2 = 0.f, a3 = 0.f;
    const float* p = g_pool + (size_t)g * HID;
    #pragma unroll 8
    for (int k = 0; k < HID; k++) {
        float v = p[k] * inv;
        a0 += v * lw[k * 4 + 0];
        a1 += v * lw[k * 4 + 1];
        a2 += v * lw[k * 4 + 2];
        a3 += v * lw[k * 4 + 3];
    }
    out[g * 4 + 0] = a0 + lb[0];
    out[g * 4 + 1] = a1 + lb[1];
    out[g * 4 + 2] = a2 + lb[2];
    out[g * 4 + 3] = a3 + lb[3];
}

// ---------------- PDL launch helper -----------------------------------------------------
template <typename F, typename... Args>
static void launch_pdl(F kern, dim3 grid, dim3 block, size_t shmem,
                       cudaStream_t st, Args... args) {
    cudaLaunchConfig_t cfg = {};
    cfg.gridDim = grid;
    cfg.blockDim = block;
    cfg.dynamicSmemBytes = shmem;
    cfg.stream = st;
    cudaLaunchAttribute attr[1];
    attr[0].id = cudaLaunchAttributeProgrammaticStreamSerialization;
    attr[0].val.programmaticStreamSerializationAllowed = 1;
    cfg.attrs = attr;
    cfg.numAttrs = 1;
    cudaLaunchKernelEx(&cfg, kern, args...);
}

// ---------------- launch ----------------------------------------------------------------
extern "C" void kernel_launch(void* const* d_in, const int* in_sizes, int n_in,
                              void* d_out, int out_size) {
    const float* pos      = (const float*)d_in[0];
    const int*   shape_id = (const int*)  d_in[1];
    const int*   color_id = (const int*)  d_in[2];
    const int*   ei       = (const int*)  d_in[3];
    const int*   et       = (const int*)  d_in[4];
    const int*   batch    = (const int*)  d_in[5];
    const float* se       = (const float*)d_in[6];
    const float* ce       = (const float*)d_in[7];
    const float* W1       = (const float*)d_in[8];
    const float* root1    = (const float*)d_in[9];
    const float* b1       = (const float*)d_in[10];
    const float* W2       = (const float*)d_in[11];
    const float* root2    = (const float*)d_in[12];
    const float* b2       = (const float*)d_in[13];
    const float* lin_w    = (const float*)d_in[14];
    const float* lin_b    = (const float*)d_in[15];
    float* out = (float*)d_out;

    __half *A1, *A2, *B1, *B2, *Y1h, *Y2h;
    float *wlast;
    cudaGetSymbolAddress((void**)&A1, g_A1);
    cudaGetSymbolAddress((void**)&A2, g_A2);
    cudaGetSymbolAddress((void**)&B1, g_B1);
    cudaGetSymbolAddress((void**)&B2, g_B2);
    cudaGetSymbolAddress((void**)&Y1h, g_Y1h);
    cudaGetSymbolAddress((void**)&Y2h, g_Y2h);
    cudaGetSymbolAddress((void**)&wlast, g_wlast);

    static cudaStream_t s2 = nullptr;
    static cudaEvent_t evFork = nullptr, evJoin = nullptr;
    if (s2 == nullptr) {
        cudaFuncSetAttribute(gemm_tc_kernel<true>,
                             cudaFuncAttributeMaxDynamicSharedMemorySize, SMEM_BYTES);
        cudaFuncSetAttribute(gemm_tc_kernel<false>,
                             cudaFuncAttributeMaxDynamicSharedMemorySize, SMEM_BYTES);
        cudaStreamCreateWithFlags(&s2, cudaStreamNonBlocking);
        cudaEventCreateWithFlags(&evFork, cudaEventDisableTiming);
        cudaEventCreateWithFlags(&evJoin, cudaEventDisableTiming);
    }

    const int TB = 256;
    dim3 gemm_grid((NN + 127) / 128, 4);
    dim3 tb(TB, 1, 1);

    // Fork side-stream for the CSR build (independent of GEMM layer 1).
    cudaEventRecord(evFork, 0);
    cudaStreamWaitEvent(s2, evFork, 0);

    // main stream: fused prep -> gemm1 (rank-1 pos update in epilogue)
    prep_kernel<<<(PREP_TOT + TB - 1) / TB, TB>>>(shape_id, color_id, se, ce,
                                                  W1, root1, W2, root2);
    launch_pdl(gemm_tc_kernel<true>, gemm_grid, tb, (size_t)SMEM_BYTES,
               (cudaStream_t)0, A1, B1, b1, pos, (const float*)wlast, Y1h);

    // side stream: CSR build
    zero_misc_kernel<<<(SEG + TB - 1) / TB, TB, 0, s2>>>();
    count_edges_kernel<<<(NE + TB - 1) / TB, TB, 0, s2>>>(ei, et);
    scan1_kernel<<<NBLK, SCAN_T, 0, s2>>>();
    scan2_kernel<<<1, SCAN_T, 0, s2>>>();
    scan3_kernel<<<(SEG + TB - 1) / TB, TB, 0, s2>>>();
    fill_csr_kernel<<<(NE + TB - 1) / TB, TB, 0, s2>>>(ei, et);
    cudaEventRecord(evJoin, s2);
    cudaStreamWaitEvent(0, evJoin, 0);

    // join: rest of the chain on main stream (PDL-chained)
    launch_pdl(aggregate_kernel<1>, dim3((NN * 32 + TB - 1) / TB), tb, (size_t)0,
               (cudaStream_t)0, batch, (const __half*)Y1h);
    launch_pdl(gemm_tc_kernel<false>, gemm_grid, tb, (size_t)SMEM_BYTES,
               (cudaStream_t)0, (const __half*)A2, (const __half*)B2, b2,
               (const float*)nullptr, (const float*)nullptr, Y2h);
    launch_pdl(aggregate_kernel<2>, dim3((NN * 32 + TB - 1) / TB), tb, (size_t)0,
               (cudaStream_t)0, batch, (const __half*)Y2h);
    launch_pdl(final_kernel, dim3((GG + TB - 1) / TB), tb, (size_t)0,
               (cudaStream_t)0, lin_w, lin_b, out);
}

// round 16
// speedup vs baseline: 1.0584x; 1.0584x over previous
#include <cuda_runtime.h>
#include <cuda_bf16.h>
#include <cuda_fp16.h>
#include <cstdint>

// Problem constants
constexpr int NN   = 50000;
constexpr int NE   = 640000;
constexpr int RR   = 3;
constexpr int HID  = 128;
constexpr int GG   = 512;
constexpr int K1   = 129;   // logical layer-1 K (row 128 handled as rank-1 update)
constexpr int KC   = 128;   // GEMM K for both layers
constexpr int SEG  = RR * NN;
constexpr int SCAN_T = 256;
constexpr int SCAN_V = 4;
constexpr int SCAN_E = SCAN_T * SCAN_V;
constexpr int NBLK = (SEG + SCAN_E - 1) / SCAN_E;

// GEMM tiling: BM=128, BN=128, BK=32, 3 stages, 256 threads (8 warps, 32x64 warp tile)
constexpr int STAGES = 3;
constexpr int RSTR   = 40;                        // row stride in halfs (80B, conflict-free)
constexpr int PLANE  = 128 * RSTR;
constexpr int STG_EL = 2 * PLANE;                 // A | B per stage
constexpr int SMEM_BYTES = STAGES * STG_EL * 2;   // 61440 B
constexpr int KT_C   = KC / 32;                   // 4 chunks

// ---------------- PDL helpers ----------------------------------------------------------
__device__ __forceinline__ void pdl_wait() {
    asm volatile("griddepcontrol.wait;" ::: "memory");
}

// ---------------- scratch -------------------------------------------------------------
__device__ __half g_A1[(size_t)NN * KC];
__device__ __half g_A2[(size_t)NN * KC];
__device__ __half g_B1[512 * KC];
__device__ __half g_B2[512 * KC];
__device__ float  g_wlast[512];                  // row 128 of [W1_0|W1_1|W1_2|root1]
__device__ __half g_Y1h[(size_t)4 * NN * HID];   // y0|y1|y2|h (fp16)
__device__ __half g_Y2h[(size_t)4 * NN * HID];
__device__ int   g_cnt[SEG];                     // node-major: seg = dst*3 + r
__device__ float g_inv[SEG];
__device__ int   g_off[SEG];
__device__ int   g_cur[SEG];
__device__ int   g_bsum[NBLK];
__device__ int   g_csr[NE];                      // packed (r << 16) | src
__device__ float g_pool[GG * HID];
__device__ int   g_gcnt[GG];

// ---------------- init / counting ------------------------------------------------------
__global__ void zero_misc_kernel() {
    int i = blockIdx.x * blockDim.x + threadIdx.x;
    if (i < SEG) g_cnt[i] = 0;
    if (i < GG * HID) g_pool[i] = 0.f;
    if (i < GG) g_gcnt[i] = 0;
}

__global__ void count_edges_kernel(const int* __restrict__ ei, const int* __restrict__ et) {
    int e = blockIdx.x * blockDim.x + threadIdx.x;
    if (e >= NE) return;
    atomicAdd(&g_cnt[ei[NE + e] * 3 + et[e]], 1);
}

// ---------------- 3-kernel exclusive scan ----------------------------------------------
__global__ void scan1_kernel() {
    __shared__ int sh[SCAN_T];
    const int tid  = threadIdx.x;
    const int base = blockIdx.x * SCAN_E + tid * SCAN_V;
    int v[SCAN_V], s = 0;
    #pragma unroll
    for (int k = 0; k < SCAN_V; k++) {
        v[k] = (base + k < SEG) ? g_cnt[base + k] : 0;
        s += v[k];
    }
    sh[tid] = s;
    __syncthreads();
    for (int off = 1; off < SCAN_T; off <<= 1) {
        int t = (tid >= off) ? sh[tid - off] : 0;
        __syncthreads();
        sh[tid] += t;
        __syncthreads();
    }
    int run = sh[tid] - s;
    #pragma unroll
    for (int k = 0; k < SCAN_V; k++) {
        if (base + k < SEG) g_off[base + k] = run;
        run += v[k];
    }
    if (tid == SCAN_T - 1) g_bsum[blockIdx.x] = sh[tid];
}

__global__ void scan2_kernel() {
    __shared__ int sh[SCAN_T];
    const int tid = threadIdx.x;
    int v = (tid < NBLK) ? g_bsum[tid] : 0;
    sh[tid] = v;
    __syncthreads();
    for (int off = 1; off < SCAN_T; off <<= 1) {
        int t = (tid >= off) ? sh[tid - off] : 0;
        __syncthreads();
        sh[tid] += t;
        __syncthreads();
    }
    if (tid < NBLK) g_bsum[tid] = sh[tid] - v;
}

__global__ void scan3_kernel() {
    int i = blockIdx.x * blockDim.x + threadIdx.x;
    if (i >= SEG) return;
    int o = g_off[i] + g_bsum[i / SCAN_E];
    g_off[i] = o;
    g_cur[i] = o;
    int c = g_cnt[i];
    g_inv[i] = 1.f / (float)(c > 0 ? c : 1);
}

__global__ void fill_csr_kernel(const int* __restrict__ ei, const int* __restrict__ et) {
    int e = blockIdx.x * blockDim.x + threadIdx.x;
    if (e >= NE) return;
    int r   = et[e];
    int dst = ei[NE + e];
    int pos = atomicAdd(&g_cur[dst * 3 + r], 1);
    g_csr[pos] = (r << 16) | ei[e];
}

// ---------------- fused prep: X1 build + B1/B2 conv + wlast ---------------------------
struct __align__(8) hf4 { __half v[4]; };

__device__ __forceinline__ void store4h(float4 v, __half* p) {
    hf4 h;
    h.v[0] = __float2half_rn(v.x);
    h.v[1] = __float2half_rn(v.y);
    h.v[2] = __float2half_rn(v.z);
    h.v[3] = __float2half_rn(v.w);
    *reinterpret_cast<hf4*>(p) = h;
}

constexpr int QW1     = KC / 4;                  // 32 quads per node
constexpr int PREP_X  = NN * QW1;
constexpr int PREP_B1 = 512 * KC;
constexpr int PREP_B2 = 512 * KC;
constexpr int PREP_WL = 512;
constexpr int PREP_TOT = PREP_X + PREP_B1 + PREP_B2 + PREP_WL;

__global__ void prep_kernel(const int* __restrict__ sid,
                            const int* __restrict__ cid,
                            const float* __restrict__ se,
                            const float* __restrict__ ce,
                            const float* __restrict__ W1, const float* __restrict__ root1,
                            const float* __restrict__ W2, const float* __restrict__ root2) {
    int idx = blockIdx.x * blockDim.x + threadIdx.x;
    if (idx < PREP_X) {
        int n = idx / QW1;
        int j = (idx - n * QW1) * 4;
        float4 v;
        if (j < 64) v = *reinterpret_cast<const float4*>(se + sid[n] * 64 + j);
        else        v = *reinterpret_cast<const float4*>(ce + cid[n] * 64 + (j - 64));
        store4h(v, &g_A1[(size_t)n * KC + j]);
    } else if (idx < PREP_X + PREP_B1) {
        int t  = idx - PREP_X;
        int nc = t / KC;
        int k  = t - nc * KC;
        int s  = nc >> 7;
        int n  = nc & 127;
        float v = (s < 3) ? W1[((size_t)s * K1 + k) * 128 + n]
                          : root1[(size_t)k * 128 + n];
        g_B1[t] = __float2half_rn(v);
    } else if (idx < PREP_X + PREP_B1 + PREP_B2) {
        int t  = idx - PREP_X - PREP_B1;
        int nc = t / KC;
        int k  = t - nc * KC;
        int s  = nc >> 7;
        int n  = nc & 127;
        float v = (s < 3) ? W2[((size_t)s * KC + k) * 128 + n]
                          : root2[(size_t)k * 128 + n];
        g_B2[t] = __float2half_rn(v);
    } else if (idx < PREP_TOT) {
        int t = idx - PREP_X - PREP_B1 - PREP_B2;   // 0..511
        int s = t >> 7;
        int n = t & 127;
        g_wlast[t] = (s < 3) ? W1[((size_t)s * K1 + 128) * 128 + n]
                             : root1[(size_t)128 * 128 + n];
    }
}

// ---------------- tensor-core GEMM (R13 3-stage pipeline) ------------------------------
__device__ __forceinline__ void cp16(uint32_t dst, const void* src) {
    asm volatile("cp.async.cg.shared.global [%0], [%1], 16;" :: "r"(dst), "l"(src));
}

__device__ __forceinline__ void mma_f16(float* c, const uint32_t* a, uint32_t b0, uint32_t b1) {
    asm volatile(
        "mma.sync.aligned.m16n8k16.row.col.f32.f16.f16.f32 "
        "{%0,%1,%2,%3}, {%4,%5,%6,%7}, {%8,%9}, {%0,%1,%2,%3};"
        : "+f"(c[0]), "+f"(c[1]), "+f"(c[2]), "+f"(c[3])
        : "r"(a[0]), "r"(a[1]), "r"(a[2]), "r"(a[3]), "r"(b0), "r"(b1));
}

__device__ __forceinline__ void ldmx4(uint32_t* r, uint32_t addr) {
    asm volatile("ldmatrix.sync.aligned.m8n8.x4.shared.b16 {%0,%1,%2,%3}, [%4];"
                 : "=r"(r[0]), "=r"(r[1]), "=r"(r[2]), "=r"(r[3]) : "r"(addr));
}

template <bool RANK1>
__global__ void __launch_bounds__(256, 2) gemm_tc_kernel(
    const __half* __restrict__ A,
    const __half* __restrict__ B,
    const float* __restrict__ bias,
    const float* __restrict__ pos,      // [N] (RANK1 only)
    const float* __restrict__ wlast,    // [512] (RANK1 only)
    __half* __restrict__ Yh)            // [4, N, 128] fp16
{
    extern __shared__ __align__(16) __half smem[];

    pdl_wait();   // predecessor (prep / aggregate) must be complete before reading A/B

    const int tid  = threadIdx.x;
    const int wid  = tid >> 5;
    const int lane = tid & 31;
    const int wm   = wid & 3;
    const int wn   = wid >> 2;
    const int m0   = blockIdx.x * 128;
    const int sec  = blockIdx.y;
    const int nrow0 = sec * 128;

    const uint32_t s_u32 = (uint32_t)__cvta_generic_to_shared(smem);

    float c[2][4][2][4] = {};

    auto load_chunk = [&](int ks, int slot) {
        const int k0 = ks * 32;
        #pragma unroll
        for (int rep = 0; rep < 4; rep++) {
            int s = tid + rep * 256;
            int plane = s >> 9;
            int rr    = (s & 511) >> 2;
            int h     = s & 3;
            const __half* src;
            bool ok = true;
            if (plane == 0) {
                ok = (m0 + rr < NN);
                src = A + (size_t)(m0 + rr) * KC + k0 + h * 8;
            } else {
                src = B + (size_t)(nrow0 + rr) * KC + k0 + h * 8;
            }
            if (ok) {
                uint32_t dst = s_u32 +
                    ((slot * STG_EL + plane * PLANE + rr * RSTR + h * 8) << 1);
                cp16(dst, src);
            }
        }
        asm volatile("cp.async.commit_group;" ::: "memory");
    };

    #pragma unroll
    for (int s = 0; s < STAGES - 1; s++) load_chunk(s, s);

    const int bgrp = lane >> 3;
    const int brow = lane & 7;
    const int bn_off = (bgrp & 2) ? 8 : 0;
    const int bk_off = (bgrp & 1) * 8;
    const int a_cof  = (lane >> 4) * 8;

    for (int ks = 0; ks < KT_C; ks++) {
        asm volatile("cp.async.wait_group %0;" :: "n"(STAGES - 2) : "memory");
        __syncthreads();

        const int nk = ks + STAGES - 1;
        if (nk < KT_C) load_chunk(nk, nk % STAGES);
        else asm volatile("cp.async.commit_group;" ::: "memory");

        const int slot = ks % STAGES;
        const uint32_t st_base = s_u32 + ((slot * STG_EL) << 1);

        #pragma unroll
        for (int kp = 0; kp < 2; kp++) {
            uint32_t ah[2][4];
            #pragma unroll
            for (int mt = 0; mt < 2; mt++) {
                int row = wm * 32 + mt * 16 + (lane & 15);
                ldmx4(ah[mt], st_base + ((row * RSTR + kp * 16 + a_cof) << 1));
            }
            #pragma unroll
            for (int ntp = 0; ntp < 4; ntp++) {
                const int n = wn * 64 + ntp * 16 + bn_off + brow;
                uint32_t bh[4];
                ldmx4(bh, st_base + ((PLANE + n * RSTR + kp * 16 + bk_off) << 1));
                #pragma unroll
                for (int mt = 0; mt < 2; mt++) {
                    mma_f16(c[mt][ntp][0], ah[mt], bh[0], bh[1]);
                    mma_f16(c[mt][ntp][1], ah[mt], bh[2], bh[3]);
                }
            }
        }
    }

    // epilogue: all sections fp16; +bias on sec 3; +pos*wlast rank-1 if RANK1
    __half* Ysec = Yh + (size_t)sec * NN * HID;
    #pragma unroll
    for (int mt = 0; mt < 2; mt++) {
        int row = m0 + wm * 32 + mt * 16 + (lane >> 2);
        float p0 = 0.f, p1 = 0.f;
        if (RANK1) {
            if (row < NN)     p0 = pos[row];
            if (row + 8 < NN) p1 = pos[row + 8];
        }
        #pragma unroll
        for (int ntp = 0; ntp < 4; ntp++) {
            #pragma unroll
            for (int ng = 0; ng < 2; ng++) {
                int col = wn * 64 + ntp * 16 + ng * 8 + (lane & 3) * 2;
                float* cc = c[mt][ntp][ng];
                float ax = 0.f, ay = 0.f;
                if (sec == 3) { ax = bias[col]; ay = bias[col + 1]; }
                if (RANK1) {
                    float wl0 = wlast[nrow0 + col];
                    float wl1 = wlast[nrow0 + col + 1];
                    cc[0] += p0 * wl0; cc[1] += p0 * wl1;
                    cc[2] += p1 * wl0; cc[3] += p1 * wl1;
                }
                if (row < NN)
                    *reinterpret_cast<__half2*>(Ysec + (size_t)row * HID + col) =
                        __floats2half2_rn(cc[0] + ax, cc[1] + ay);
                if (row + 8 < NN)
                    *reinterpret_cast<__half2*>(Ysec + (size_t)(row + 8) * HID + col) =
                        __floats2half2_rn(cc[2] + ax, cc[3] + ay);
            }
        }
    }
}

// ---------------- CSR gather aggregation: merged node-major loop ----------------------
template <int LAYER>
__global__ void aggregate_kernel(const int* __restrict__ batch,
                                 const __half* __restrict__ Yh) {
    pdl_wait();   // gemm must be complete before gathering Yh

    const int w = (blockIdx.x * blockDim.x + threadIdx.x) >> 5;
    if (w >= NN) return;
    const int lane = threadIdx.x & 31;
    const int lo8 = lane * 4;

    float4 acc;
    {
        uint2 raw = *reinterpret_cast<const uint2*>(
            Yh + (size_t)3 * NN * HID + (size_t)w * HID + lo8);
        float2 a = __half22float2(*reinterpret_cast<const __half2*>(&raw.x));
        float2 b = __half22float2(*reinterpret_cast<const __half2*>(&raw.y));
        acc = make_float4(a.x, a.y, b.x, b.y);
    }

    const int base3 = w * 3;
    const int s0  = g_off[base3];
    const int end = g_off[base3 + 2] + g_cnt[base3 + 2];
    const float sc0 = g_inv[base3];
    const float sc1 = g_inv[base3 + 1];
    const float sc2 = g_inv[base3 + 2];

    for (int i = s0; i < end; i++) {
        int p   = g_csr[i];
        int r   = p >> 16;
        int src = p & 0xFFFF;
        float s = (r == 0) ? sc0 : ((r == 1) ? sc1 : sc2);
        uint2 raw = *reinterpret_cast<const uint2*>(
            Yh + ((size_t)r * NN + src) * HID + lo8);
        float2 a = __half22float2(*reinterpret_cast<const __half2*>(&raw.x));
        float2 b = __half22float2(*reinterpret_cast<const __half2*>(&raw.y));
        acc.x = fmaf(a.x, s, acc.x);
        acc.y = fmaf(a.y, s, acc.y);
        acc.z = fmaf(b.x, s, acc.z);
        acc.w = fmaf(b.y, s, acc.w);
    }

    acc.x = fmaxf(acc.x, 0.f); acc.y = fmaxf(acc.y, 0.f);
    acc.z = fmaxf(acc.z, 0.f); acc.w = fmaxf(acc.w, 0.f);

    if (LAYER == 1) {
        store4h(acc, &g_A2[(size_t)w * KC + lo8]);
    } else {
        const int g = batch[w];
        float* o = g_pool + (size_t)g * HID + lo8;
        asm volatile("red.global.add.v4.f32 [%0], {%1, %2, %3, %4};"
                     :: "l"(o), "f"(acc.x), "f"(acc.y), "f"(acc.z), "f"(acc.w) : "memory");
        if (lane == 0) atomicAdd(&g_gcnt[g], 1);
    }
}

__global__ void final_kernel(const float* __restrict__ lw, const float* __restrict__ lb,
                             float* __restrict__ out) {
    pdl_wait();
    int g = blockIdx.x * blockDim.x + threadIdx.x;
    if (g >= GG) return;
    const int c = g_gcnt[g];
    const float inv = 1.f / (float)(c > 0 ? c : 1);
    float a0 = 0.f, a1 = 0.f, a2 = 0.f, a3 = 0.f;
    const float* p = g_pool + (size_t)g * HID;
    #pragma unroll 8
    for (int k = 0; k < HID; k++) {
        float v = p[k] * inv;
        a0 += v * lw[k * 4 + 0];
        a1 += v * lw[k * 4 + 1];
        a2 += v * lw[k * 4 + 2];
        a3 += v * lw[k * 4 + 3];
    }
    out[g * 4 + 0] = a0 + lb[0];
    out[g * 4 + 1] = a1 + lb[1];
    out[g * 4 + 2] = a2 + lb[2];
    out[g * 4 + 3] = a3 + lb[3];
}

// ---------------- PDL launch helper -----------------------------------------------------
template <typename F, typename... Args>
static void launch_pdl(F kern, dim3 grid, dim3 block, size_t shmem,
                       cudaStream_t st, Args... args) {
    cudaLaunchConfig_t cfg = {};
    cfg.gridDim = grid;
    cfg.blockDim = block;
    cfg.dynamicSmemBytes = shmem;
    cfg.stream = st;
    cudaLaunchAttribute attr[1];
    attr[0].id = cudaLaunchAttributeProgrammaticStreamSerialization;
    attr[0].val.programmaticStreamSerializationAllowed = 1;
    cfg.attrs = attr;
    cfg.numAttrs = 1;
    cudaLaunchKernelEx(&cfg, kern, args...);
}

// ---------------- launch ----------------------------------------------------------------
extern "C" void kernel_launch(void* const* d_in, const int* in_sizes, int n_in,
                              void* d_out, int out_size) {
    const float* pos      = (const float*)d_in[0];
    const int*   shape_id = (const int*)  d_in[1];
    const int*   color_id = (const int*)  d_in[2];
    const int*   ei       = (const int*)  d_in[3];
    const int*   et       = (const int*)  d_in[4];
    const int*   batch    = (const int*)  d_in[5];
    const float* se       = (const float*)d_in[6];
    const float* ce       = (const float*)d_in[7];
    const float* W1       = (const float*)d_in[8];
    const float* root1    = (const float*)d_in[9];
    const float* b1       = (const float*)d_in[10];
    const float* W2       = (const float*)d_in[11];
    const float* root2    = (const float*)d_in[12];
    const float* b2       = (const float*)d_in[13];
    const float* lin_w    = (const float*)d_in[14];
    const float* lin_b    = (const float*)d_in[15];
    float* out = (float*)d_out;

    __half *A1, *A2, *B1, *B2, *Y1h, *Y2h;
    float *wlast;
    cudaGetSymbolAddress((void**)&A1, g_A1);
    cudaGetSymbolAddress((void**)&A2, g_A2);
    cudaGetSymbolAddress((void**)&B1, g_B1);
    cudaGetSymbolAddress((void**)&B2, g_B2);
    cudaGetSymbolAddress((void**)&Y1h, g_Y1h);
    cudaGetSymbolAddress((void**)&Y2h, g_Y2h);
    cudaGetSymbolAddress((void**)&wlast, g_wlast);

    static cudaStream_t s2 = nullptr;
    static cudaEvent_t evFork = nullptr, evJoin = nullptr;
    if (s2 == nullptr) {
        cudaFuncSetAttribute(gemm_tc_kernel<true>,
                             cudaFuncAttributeMaxDynamicSharedMemorySize, SMEM_BYTES);
        cudaFuncSetAttribute(gemm_tc_kernel<false>,
                             cudaFuncAttributeMaxDynamicSharedMemorySize, SMEM_BYTES);
        cudaStreamCreateWithFlags(&s2, cudaStreamNonBlocking);
        cudaEventCreateWithFlags(&evFork, cudaEventDisableTiming);
        cudaEventCreateWithFlags(&evJoin, cudaEventDisableTiming);
    }

    const int TB = 256;
    dim3 gemm_grid((NN + 127) / 128, 4);
    dim3 tb(TB, 1, 1);

    // Fork side-stream for the CSR build (independent of GEMM layer 1).
    cudaEventRecord(evFork, 0);
    cudaStreamWaitEvent(s2, evFork, 0);

    // main stream: fused prep -> gemm1 (rank-1 pos update in epilogue)
    prep_kernel<<<(PREP_TOT + TB - 1) / TB, TB>>>(shape_id, color_id, se, ce,
                                                  W1, root1, W2, root2);
    launch_pdl(gemm_tc_kernel<true>, gemm_grid, tb, (size_t)SMEM_BYTES,
               (cudaStream_t)0, A1, B1, b1, pos, (const float*)wlast, Y1h);

    // side stream: CSR build
    zero_misc_kernel<<<(SEG + TB - 1) / TB, TB, 0, s2>>>();
    count_edges_kernel<<<(NE + TB - 1) / TB, TB, 0, s2>>>(ei, et);
    scan1_kernel<<<NBLK, SCAN_T, 0, s2>>>();
    scan2_kernel<<<1, SCAN_T, 0, s2>>>();
    scan3_kernel<<<(SEG + TB - 1) / TB, TB, 0, s2>>>();
    fill_csr_kernel<<<(NE + TB - 1) / TB, TB, 0, s2>>>(ei, et);
    cudaEventRecord(evJoin, s2);
    cudaStreamWaitEvent(0, evJoin, 0);

    // join: rest of the chain on main stream (PDL-chained)
    launch_pdl(aggregate_kernel<1>, dim3((NN * 32 + TB - 1) / TB), tb, (size_t)0,
               (cudaStream_t)0, batch, (const __half*)Y1h);
    launch_pdl(gemm_tc_kernel<false>, gemm_grid, tb, (size_t)SMEM_BYTES,
               (cudaStream_t)0, (const __half*)A2, (const __half*)B2, b2,
               (const float*)nullptr, (const float*)nullptr, Y2h);
    launch_pdl(aggregate_kernel<2>, dim3((NN * 32 + TB - 1) / TB), tb, (size_t)0,
               (cudaStream_t)0, batch, (const __half*)Y2h);
    launch_pdl(final_kernel, dim3((GG + TB - 1) / TB), tb, (size_t)0,
               (cudaStream_t)0, lin_w, lin_b, out);
}

// round 17
// speedup vs baseline: 1.0613x; 1.0027x over previous
#include <cuda_runtime.h>
#include <cuda_bf16.h>
#include <cuda_fp16.h>
#include <cstdint>

// Problem constants
constexpr int NN   = 50000;
constexpr int NE   = 640000;
constexpr int RR   = 3;
constexpr int HID  = 128;
constexpr int GG   = 512;
constexpr int K1   = 129;   // logical layer-1 K (row 128 handled as rank-1 update)
constexpr int KC   = 128;   // GEMM K for both layers
constexpr int SEG  = RR * NN;
constexpr int SCAN_T = 256;
constexpr int SCAN_V = 4;
constexpr int SCAN_E = SCAN_T * SCAN_V;
constexpr int NBLK = (SEG + SCAN_E - 1) / SCAN_E;

// GEMM v10: BM=128, BK=32, A-resident (4 chunk planes), B streamed over
// 8 (section,chunk) steps with 3 B slots. grid.y = 2 section-pairs.
constexpr int RSTR    = 40;                      // row stride in halfs (80B)
constexpr int A_PLANE = 128 * RSTR;              // elems per A chunk plane (5120)
constexpr int B_BASE  = 4 * A_PLANE;             // B slot base (elems)
constexpr int BSTG    = A_PLANE;                 // elems per B slot
constexpr int SMEM_BYTES = (B_BASE + 3 * BSTG) * 2;   // 71680 B
constexpr int KT_C    = KC / 32;                 // 4 chunks
constexpr int NSTEPS  = 2 * KT_C;                // 8 (2 sections per CTA)

// ---------------- PDL helpers ----------------------------------------------------------
__device__ __forceinline__ void pdl_wait() {
    asm volatile("griddepcontrol.wait;" ::: "memory");
}

// ---------------- scratch -------------------------------------------------------------
__device__ __half g_A1[(size_t)NN * KC];
__device__ __half g_A2[(size_t)NN * KC];
__device__ __half g_B1[512 * KC];
__device__ __half g_B2[512 * KC];
__device__ float  g_wlast[512];                  // row 128 of [W1_0|W1_1|W1_2|root1]
__device__ __half g_Y1h[(size_t)4 * NN * HID];   // y0|y1|y2|h (fp16)
__device__ __half g_Y2h[(size_t)4 * NN * HID];
__device__ int   g_cnt[SEG];                     // node-major: seg = dst*3 + r
__device__ float g_inv[SEG];
__device__ int   g_off[SEG];
__device__ int   g_cur[SEG];
__device__ int   g_bsum[NBLK];
__device__ int   g_csr[NE];                      // packed (r << 16) | src
__device__ float g_pool[GG * HID];
__device__ int   g_gcnt[GG];

// ---------------- init / counting ------------------------------------------------------
__global__ void zero_misc_kernel() {
    int i = blockIdx.x * blockDim.x + threadIdx.x;
    if (i < SEG) g_cnt[i] = 0;
    if (i < GG * HID) g_pool[i] = 0.f;
    if (i < GG) g_gcnt[i] = 0;
}

__global__ void count_edges_kernel(const int* __restrict__ ei, const int* __restrict__ et) {
    int e = blockIdx.x * blockDim.x + threadIdx.x;
    if (e >= NE) return;
    atomicAdd(&g_cnt[ei[NE + e] * 3 + et[e]], 1);
}

// ---------------- 3-kernel exclusive scan ----------------------------------------------
__global__ void scan1_kernel() {
    __shared__ int sh[SCAN_T];
    const int tid  = threadIdx.x;
    const int base = blockIdx.x * SCAN_E + tid * SCAN_V;
    int v[SCAN_V], s = 0;
    #pragma unroll
    for (int k = 0; k < SCAN_V; k++) {
        v[k] = (base + k < SEG) ? g_cnt[base + k] : 0;
        s += v[k];
    }
    sh[tid] = s;
    __syncthreads();
    for (int off = 1; off < SCAN_T; off <<= 1) {
        int t = (tid >= off) ? sh[tid - off] : 0;
        __syncthreads();
        sh[tid] += t;
        __syncthreads();
    }
    int run = sh[tid] - s;
    #pragma unroll
    for (int k = 0; k < SCAN_V; k++) {
        if (base + k < SEG) g_off[base + k] = run;
        run += v[k];
    }
    if (tid == SCAN_T - 1) g_bsum[blockIdx.x] = sh[tid];
}

__global__ void scan2_kernel() {
    __shared__ int sh[SCAN_T];
    const int tid = threadIdx.x;
    int v = (tid < NBLK) ? g_bsum[tid] : 0;
    sh[tid] = v;
    __syncthreads();
    for (int off = 1; off < SCAN_T; off <<= 1) {
        int t = (tid >= off) ? sh[tid - off] : 0;
        __syncthreads();
        sh[tid] += t;
        __syncthreads();
    }
    if (tid < NBLK) g_bsum[tid] = sh[tid] - v;
}

__global__ void scan3_kernel() {
    int i = blockIdx.x * blockDim.x + threadIdx.x;
    if (i >= SEG) return;
    int o = g_off[i] + g_bsum[i / SCAN_E];
    g_off[i] = o;
    g_cur[i] = o;
    int c = g_cnt[i];
    g_inv[i] = 1.f / (float)(c > 0 ? c : 1);
}

__global__ void fill_csr_kernel(const int* __restrict__ ei, const int* __restrict__ et) {
    int e = blockIdx.x * blockDim.x + threadIdx.x;
    if (e >= NE) return;
    int r   = et[e];
    int dst = ei[NE + e];
    int pos = atomicAdd(&g_cur[dst * 3 + r], 1);
    g_csr[pos] = (r << 16) | ei[e];
}

// ---------------- fused prep: X1 build + B1/B2 conv + wlast ---------------------------
struct __align__(8) hf4 { __half v[4]; };

__device__ __forceinline__ void store4h(float4 v, __half* p) {
    hf4 h;
    h.v[0] = __float2half_rn(v.x);
    h.v[1] = __float2half_rn(v.y);
    h.v[2] = __float2half_rn(v.z);
    h.v[3] = __float2half_rn(v.w);
    *reinterpret_cast<hf4*>(p) = h;
}

constexpr int QW1     = KC / 4;                  // 32 quads per node
constexpr int PREP_X  = NN * QW1;
constexpr int PREP_B1 = 512 * KC;
constexpr int PREP_B2 = 512 * KC;
constexpr int PREP_WL = 512;
constexpr int PREP_TOT = PREP_X + PREP_B1 + PREP_B2 + PREP_WL;

__global__ void prep_kernel(const int* __restrict__ sid,
                            const int* __restrict__ cid,
                            const float* __restrict__ se,
                            const float* __restrict__ ce,
                            const float* __restrict__ W1, const float* __restrict__ root1,
                            const float* __restrict__ W2, const float* __restrict__ root2) {
    int idx = blockIdx.x * blockDim.x + threadIdx.x;
    if (idx < PREP_X) {
        int n = idx / QW1;
        int j = (idx - n * QW1) * 4;
        float4 v;
        if (j < 64) v = *reinterpret_cast<const float4*>(se + sid[n] * 64 + j);
        else        v = *reinterpret_cast<const float4*>(ce + cid[n] * 64 + (j - 64));
        store4h(v, &g_A1[(size_t)n * KC + j]);
    } else if (idx < PREP_X + PREP_B1) {
        int t  = idx - PREP_X;
        int nc = t / KC;
        int k  = t - nc * KC;
        int s  = nc >> 7;
        int n  = nc & 127;
        float v = (s < 3) ? W1[((size_t)s * K1 + k) * 128 + n]
                          : root1[(size_t)k * 128 + n];
        g_B1[t] = __float2half_rn(v);
    } else if (idx < PREP_X + PREP_B1 + PREP_B2) {
        int t  = idx - PREP_X - PREP_B1;
        int nc = t / KC;
        int k  = t - nc * KC;
        int s  = nc >> 7;
        int n  = nc & 127;
        float v = (s < 3) ? W2[((size_t)s * KC + k) * 128 + n]
                          : root2[(size_t)k * 128 + n];
        g_B2[t] = __float2half_rn(v);
    } else if (idx < PREP_TOT) {
        int t = idx - PREP_X - PREP_B1 - PREP_B2;   // 0..511
        int s = t >> 7;
        int n = t & 127;
        g_wlast[t] = (s < 3) ? W1[((size_t)s * K1 + 128) * 128 + n]
                             : root1[(size_t)128 * 128 + n];
    }
}

// ---------------- tensor-core GEMM v10: A-resident, B streamed over sections ----------
__device__ __forceinline__ void cp16(uint32_t dst, const void* src) {
    asm volatile("cp.async.cg.shared.global [%0], [%1], 16;" :: "r"(dst), "l"(src));
}

__device__ __forceinline__ void mma_f16(float* c, const uint32_t* a, uint32_t b0, uint32_t b1) {
    asm volatile(
        "mma.sync.aligned.m16n8k16.row.col.f32.f16.f16.f32 "
        "{%0,%1,%2,%3}, {%4,%5,%6,%7}, {%8,%9}, {%0,%1,%2,%3};"
        : "+f"(c[0]), "+f"(c[1]), "+f"(c[2]), "+f"(c[3])
        : "r"(a[0]), "r"(a[1]), "r"(a[2]), "r"(a[3]), "r"(b0), "r"(b1));
}

__device__ __forceinline__ void ldmx4(uint32_t* r, uint32_t addr) {
    asm volatile("ldmatrix.sync.aligned.m8n8.x4.shared.b16 {%0,%1,%2,%3}, [%4];"
                 : "=r"(r[0]), "=r"(r[1]), "=r"(r[2]), "=r"(r[3]) : "r"(addr));
}

template <bool RANK1>
__global__ void __launch_bounds__(256, 2) gemm_tc_kernel(
    const __half* __restrict__ A,
    const __half* __restrict__ B,
    const float* __restrict__ bias,
    const float* __restrict__ pos,      // [N] (RANK1 only)
    const float* __restrict__ wlast,    // [512] (RANK1 only)
    __half* __restrict__ Yh)            // [4, N, 128] fp16
{
    extern __shared__ __align__(16) __half smem[];

    pdl_wait();   // predecessor (prep / aggregate) must be complete before reading A/B

    const int tid  = threadIdx.x;
    const int wid  = tid >> 5;
    const int lane = tid & 31;
    const int wm   = wid & 3;
    const int wn   = wid >> 2;
    const int m0   = blockIdx.x * 128;
    const int byp  = blockIdx.y;        // section pair: 0 -> secs {0,1}, 1 -> {2,3}

    const uint32_t s_u32 = (uint32_t)__cvta_generic_to_shared(smem);

    float c[2][4][2][4] = {};

    // B loader: step s covers section (byp*2 + (s>>2)), k-chunk (s&3); 2 cp.async/thread
    auto load_b = [&](int s, int slot) {
        const int sec = byp * 2 + (s >> 2);
        const int k0  = (s & 3) * 32;
        const int nrow0 = sec * 128;
        #pragma unroll
        for (int rep = 0; rep < 2; rep++) {
            int ch = tid + rep * 256;          // 0..511
            int rr = ch >> 2;
            int h  = ch & 3;
            const __half* src = B + (size_t)(nrow0 + rr) * KC + k0 + h * 8;
            uint32_t dst = s_u32 + ((B_BASE + slot * BSTG + rr * RSTR + h * 8) << 1);
            cp16(dst, src);
        }
        asm volatile("cp.async.commit_group;" ::: "memory");
    };

    // Prologue: all 4 A chunk planes + B step 0 (group 0), then B step 1 (group 1)
    #pragma unroll
    for (int ks = 0; ks < KT_C; ks++) {
        const int k0 = ks * 32;
        #pragma unroll
        for (int rep = 0; rep < 2; rep++) {
            int ch = tid + rep * 256;
            int rr = ch >> 2;
            int h  = ch & 3;
            if (m0 + rr < NN) {
                const __half* src = A + (size_t)(m0 + rr) * KC + k0 + h * 8;
                uint32_t dst = s_u32 + ((ks * A_PLANE + rr * RSTR + h * 8) << 1);
                cp16(dst, src);
            }
        }
    }
    load_b(0, 0);      // commit: A + B0
    load_b(1, 1);      // commit: B1

    const int bgrp = lane >> 3;
    const int brow = lane & 7;
    const int bn_off = (bgrp & 2) ? 8 : 0;
    const int bk_off = (bgrp & 1) * 8;
    const int a_cof  = (lane >> 4) * 8;

    for (int s = 0; s < NSTEPS; s++) {
        asm volatile("cp.async.wait_group 1;" ::: "memory");
        __syncthreads();

        const int ns = s + 2;
        if (ns < NSTEPS) load_b(ns, ns % 3);
        else asm volatile("cp.async.commit_group;" ::: "memory");

        const uint32_t a_base = s_u32 + (((s & 3) * A_PLANE) << 1);
        const uint32_t b_base = s_u32 + ((B_BASE + (s % 3) * BSTG) << 1);

        #pragma unroll
        for (int kp = 0; kp < 2; kp++) {
            uint32_t ah[2][4];
            #pragma unroll
            for (int mt = 0; mt < 2; mt++) {
                int row = wm * 32 + mt * 16 + (lane & 15);
                ldmx4(ah[mt], a_base + ((row * RSTR + kp * 16 + a_cof) << 1));
            }
            #pragma unroll
            for (int ntp = 0; ntp < 4; ntp++) {
                const int n = wn * 64 + ntp * 16 + bn_off + brow;
                uint32_t bh[4];
                ldmx4(bh, b_base + ((n * RSTR + kp * 16 + bk_off) << 1));
                #pragma unroll
                for (int mt = 0; mt < 2; mt++) {
                    mma_f16(c[mt][ntp][0], ah[mt], bh[0], bh[1]);
                    mma_f16(c[mt][ntp][1], ah[mt], bh[2], bh[3]);
                }
            }
        }

        // section epilogue after its last chunk
        if ((s & 3) == 3) {
            const int sec = byp * 2 + (s >> 2);
            const int nrow0 = sec * 128;
            __half* Ysec = Yh + (size_t)sec * NN * HID;
            #pragma unroll
            for (int mt = 0; mt < 2; mt++) {
                int row = m0 + wm * 32 + mt * 16 + (lane >> 2);
                float p0 = 0.f, p1 = 0.f;
                if (RANK1) {
                    if (row < NN)     p0 = pos[row];
                    if (row + 8 < NN) p1 = pos[row + 8];
                }
                #pragma unroll
                for (int ntp = 0; ntp < 4; ntp++) {
                    #pragma unroll
                    for (int ng = 0; ng < 2; ng++) {
                        int col = wn * 64 + ntp * 16 + ng * 8 + (lane & 3) * 2;
                        float* cc = c[mt][ntp][ng];
                        float ax = 0.f, ay = 0.f;
                        if (sec == 3) { ax = bias[col]; ay = bias[col + 1]; }
                        if (RANK1) {
                            float wl0 = wlast[nrow0 + col];
                            float wl1 = wlast[nrow0 + col + 1];
                            cc[0] += p0 * wl0; cc[1] += p0 * wl1;
                            cc[2] += p1 * wl0; cc[3] += p1 * wl1;
                        }
                        if (row < NN)
                            *reinterpret_cast<__half2*>(Ysec + (size_t)row * HID + col) =
                                __floats2half2_rn(cc[0] + ax, cc[1] + ay);
                        if (row + 8 < NN)
                            *reinterpret_cast<__half2*>(Ysec + (size_t)(row + 8) * HID + col) =
                                __floats2half2_rn(cc[2] + ax, cc[3] + ay);
                        cc[0] = 0.f; cc[1] = 0.f; cc[2] = 0.f; cc[3] = 0.f;
                    }
                }
            }
        }
    }
}

// ---------------- CSR gather aggregation: merged node-major loop ----------------------
template <int LAYER>
__global__ void aggregate_kernel(const int* __restrict__ batch,
                                 const __half* __restrict__ Yh) {
    pdl_wait();   // gemm must be complete before gathering Yh

    const int w = (blockIdx.x * blockDim.x + threadIdx.x) >> 5;
    if (w >= NN) return;
    const int lane = threadIdx.x & 31;
    const int lo8 = lane * 4;

    float4 acc;
    {
        uint2 raw = *reinterpret_cast<const uint2*>(
            Yh + (size_t)3 * NN * HID + (size_t)w * HID + lo8);
        float2 a = __half22float2(*reinterpret_cast<const __half2*>(&raw.x));
        float2 b = __half22float2(*reinterpret_cast<const __half2*>(&raw.y));
        acc = make_float4(a.x, a.y, b.x, b.y);
    }

    const int base3 = w * 3;
    const int s0  = g_off[base3];
    const int end = g_off[base3 + 2] + g_cnt[base3 + 2];
    const float sc0 = g_inv[base3];
    const float sc1 = g_inv[base3 + 1];
    const float sc2 = g_inv[base3 + 2];

    for (int i = s0; i < end; i++) {
        int p   = g_csr[i];
        int r   = p >> 16;
        int src = p & 0xFFFF;
        float s = (r == 0) ? sc0 : ((r == 1) ? sc1 : sc2);
        uint2 raw = *reinterpret_cast<const uint2*>(
            Yh + ((size_t)r * NN + src) * HID + lo8);
        float2 a = __half22float2(*reinterpret_cast<const __half2*>(&raw.x));
        float2 b = __half22float2(*reinterpret_cast<const __half2*>(&raw.y));
        acc.x = fmaf(a.x, s, acc.x);
        acc.y = fmaf(a.y, s, acc.y);
        acc.z = fmaf(b.x, s, acc.z);
        acc.w = fmaf(b.y, s, acc.w);
    }

    acc.x = fmaxf(acc.x, 0.f); acc.y = fmaxf(acc.y, 0.f);
    acc.z = fmaxf(acc.z, 0.f); acc.w = fmaxf(acc.w, 0.f);

    if (LAYER == 1) {
        store4h(acc, &g_A2[(size_t)w * KC + lo8]);
    } else {
        const int g = batch[w];
        float* o = g_pool + (size_t)g * HID + lo8;
        asm volatile("red.global.add.v4.f32 [%0], {%1, %2, %3, %4};"
                     :: "l"(o), "f"(acc.x), "f"(acc.y), "f"(acc.z), "f"(acc.w) : "memory");
        if (lane == 0) atomicAdd(&g_gcnt[g], 1);
    }
}

__global__ void final_kernel(const float* __restrict__ lw, const float* __restrict__ lb,
                             float* __restrict__ out) {
    pdl_wait();
    int g = blockIdx.x * blockDim.x + threadIdx.x;
    if (g >= GG) return;
    const int c = g_gcnt[g];
    const float inv = 1.f / (float)(c > 0 ? c : 1);
    float a0 = 0.f, a1 = 0.f, a2 = 0.f, a3 = 0.f;
    const float* p = g_pool + (size_t)g * HID;
    #pragma unroll 8
    for (int k = 0; k < HID; k++) {
        float v = p[k] * inv;
        a0 += v * lw[k * 4 + 0];
        a1 += v * lw[k * 4 + 1];
        a2 += v * lw[k * 4 + 2];
        a3 += v * lw[k * 4 + 3];
    }
    out[g * 4 + 0] = a0 + lb[0];
    out[g * 4 + 1] = a1 + lb[1];
    out[g * 4 + 2] = a2 + lb[2];
    out[g * 4 + 3] = a3 + lb[3];
}

// ---------------- PDL launch helper -----------------------------------------------------
template <typename F, typename... Args>
static void launch_pdl(F kern, dim3 grid, dim3 block, size_t shmem,
                       cudaStream_t st, Args... args) {
    cudaLaunchConfig_t cfg = {};
    cfg.gridDim = grid;
    cfg.blockDim = block;
    cfg.dynamicSmemBytes = shmem;
    cfg.stream = st;
    cudaLaunchAttribute attr[1];
    attr[0].id = cudaLaunchAttributeProgrammaticStreamSerialization;
    attr[0].val.programmaticStreamSerializationAllowed = 1;
    cfg.attrs = attr;
    cfg.numAttrs = 1;
    cudaLaunchKernelEx(&cfg, kern, args...);
}

// ---------------- launch ----------------------------------------------------------------
extern "C" void kernel_launch(void* const* d_in, const int* in_sizes, int n_in,
                              void* d_out, int out_size) {
    const float* pos      = (const float*)d_in[0];
    const int*   shape_id = (const int*)  d_in[1];
    const int*   color_id = (const int*)  d_in[2];
    const int*   ei       = (const int*)  d_in[3];
    const int*   et       = (const int*)  d_in[4];
    const int*   batch    = (const int*)  d_in[5];
    const float* se       = (const float*)d_in[6];
    const float* ce       = (const float*)d_in[7];
    const float* W1       = (const float*)d_in[8];
    const float* root1    = (const float*)d_in[9];
    const float* b1       = (const float*)d_in[10];
    const float* W2       = (const float*)d_in[11];
    const float* root2    = (const float*)d_in[12];
    const float* b2       = (const float*)d_in[13];
    const float* lin_w    = (const float*)d_in[14];
    const float* lin_b    = (const float*)d_in[15];
    float* out = (float*)d_out;

    __half *A1, *A2, *B1, *B2, *Y1h, *Y2h;
    float *wlast;
    cudaGetSymbolAddress((void**)&A1, g_A1);
    cudaGetSymbolAddress((void**)&A2, g_A2);
    cudaGetSymbolAddress((void**)&B1, g_B1);
    cudaGetSymbolAddress((void**)&B2, g_B2);
    cudaGetSymbolAddress((void**)&Y1h, g_Y1h);
    cudaGetSymbolAddress((void**)&Y2h, g_Y2h);
    cudaGetSymbolAddress((void**)&wlast, g_wlast);

    static cudaStream_t s2 = nullptr;
    static cudaEvent_t evFork = nullptr, evJoin = nullptr;
    if (s2 == nullptr) {
        cudaFuncSetAttribute(gemm_tc_kernel<true>,
                             cudaFuncAttributeMaxDynamicSharedMemorySize, SMEM_BYTES);
        cudaFuncSetAttribute(gemm_tc_kernel<false>,
                             cudaFuncAttributeMaxDynamicSharedMemorySize, SMEM_BYTES);
        cudaStreamCreateWithFlags(&s2, cudaStreamNonBlocking);
        cudaEventCreateWithFlags(&evFork, cudaEventDisableTiming);
        cudaEventCreateWithFlags(&evJoin, cudaEventDisableTiming);
    }

    const int TB = 256;
    dim3 gemm_grid((NN + 127) / 128, 2);
    dim3 tb(TB, 1, 1);

    // Fork side-stream for the CSR build (independent of GEMM layer 1).
    cudaEventRecord(evFork, 0);
    cudaStreamWaitEvent(s2, evFork, 0);

    // main stream: fused prep -> gemm1 (rank-1 pos update in epilogue)
    prep_kernel<<<(PREP_TOT + TB - 1) / TB, TB>>>(shape_id, color_id, se, ce,
                                                  W1, root1, W2, root2);
    launch_pdl(gemm_tc_kernel<true>, gemm_grid, tb, (size_t)SMEM_BYTES,
               (cudaStream_t)0, A1, B1, b1, pos, (const float*)wlast, Y1h);

    // side stream: CSR build
    zero_misc_kernel<<<(SEG + TB - 1) / TB, TB, 0, s2>>>();
    count_edges_kernel<<<(NE + TB - 1) / TB, TB, 0, s2>>>(ei, et);
    scan1_kernel<<<NBLK, SCAN_T, 0, s2>>>();
    scan2_kernel<<<1, SCAN_T, 0, s2>>>();
    scan3_kernel<<<(SEG + TB - 1) / TB, TB, 0, s2>>>();
    fill_csr_kernel<<<(NE + TB - 1) / TB, TB, 0, s2>>>(ei, et);
    cudaEventRecord(evJoin, s2);
    cudaStreamWaitEvent(0, evJoin, 0);

    // join: rest of the chain on main stream (PDL-chained)
    launch_pdl(aggregate_kernel<1>, dim3((NN * 32 + TB - 1) / TB), tb, (size_t)0,
               (cudaStream_t)0, batch, (const __half*)Y1h);
    launch_pdl(gemm_tc_kernel<false>, gemm_grid, tb, (size_t)SMEM_BYTES,
               (cudaStream_t)0, (const __half*)A2, (const __half*)B2, b2,
               (const float*)nullptr, (const float*)nullptr, Y2h);
    launch_pdl(aggregate_kernel<2>, dim3((NN * 32 + TB - 1) / TB), tb, (size_t)0,
               (cudaStream_t)0, batch, (const __half*)Y2h);
    launch_pdl(final_kernel, dim3((GG + TB - 1) / TB), tb, (size_t)0,
               (cudaStream_t)0, lin_w, lin_b, out);
}